// round 11
// baseline (speedup 1.0000x reference)
#include <cuda_runtime.h>
#include <cuda_fp16.h>
#include <cstdint>
#include <math.h>

// Problem constants
#define B_   4
#define L_   2048
#define DM   1024
#define H_   16
#define HD   64
#define M_   (B_ * L_)       // 8192 rows
#define EPSC 1e-6f
#define CH   64              // scan chunk length
#define NCH  (L_ / CH)       // 32 chunks

// GEMM constants: CTA tile 128(m) x 256(n), warp tile 64x64, BK=64
#define KC        64                  // fp16 K elems per chunk (128 B rows)
#define KCHUNKS   (DM / KC)           // 16
#define TLA       16384               // A tile: 128 rows x 128 B
#define TLB       32768               // B tile: 256 rows x 128 B
#define STG_B     (TLA + TLB)         // 48 KB
#define NSTG      3
#define SMEM_GEMM (NSTG * STG_B)      // 144 KB, occ 1

// ---------------------------------------------------------------------------
// Scratch (allocation-free rule: __device__ globals)
// ---------------------------------------------------------------------------
__device__ float g_Q[(size_t)M_ * DM];
__device__ float g_K[(size_t)M_ * DM];
__device__ float g_V[(size_t)M_ * DM];
__device__ float g_S[(size_t)B_ * H_ * NCH * HD * HD]; // chunk S sums -> prefix
__device__ float g_Z[(size_t)B_ * H_ * NCH * HD];      // chunk Z sums -> prefix
__device__ __half g_A16[(size_t)3 * M_ * DM];          // fp16 A, 3 slabs (q,k,v / attn)
__device__ __half g_W16[(size_t)4 * DM * DM];          // [N,K] fp16, 4 slabs (q,k,v,o)

// ---------------------------------------------------------------------------
// PTX helpers (base-target sm_103-safe: cp.async, ldmatrix, mma.sync only)
// ---------------------------------------------------------------------------
__device__ __forceinline__ uint32_t smem_u32(const void* p) {
    uint32_t a;
    asm("{ .reg .u64 t; cvta.to.shared.u64 t, %1; cvt.u32.u64 %0, t; }" : "=r"(a) : "l"(p));
    return a;
}
__device__ __forceinline__ void cp16(uint32_t saddr, const void* g) {
    asm volatile("cp.async.cg.shared.global [%0], [%1], 16;\n" :: "r"(saddr), "l"(g));
}
#define CP_COMMIT() asm volatile("cp.async.commit_group;\n")
#define CP_WAIT2()  asm volatile("cp.async.wait_group 2;\n")

__device__ __forceinline__ void ldsm4(uint32_t* r, uint32_t addr) {
    asm volatile("ldmatrix.sync.aligned.m8n8.x4.shared.b16 {%0,%1,%2,%3}, [%4];"
                 : "=r"(r[0]), "=r"(r[1]), "=r"(r[2]), "=r"(r[3]) : "r"(addr));
}
__device__ __forceinline__ void mma16816(float* d, const uint32_t* a,
                                         uint32_t b0, uint32_t b1) {
    asm volatile(
        "mma.sync.aligned.m16n8k16.row.col.f32.f16.f16.f32 "
        "{%0,%1,%2,%3}, {%4,%5,%6,%7}, {%8,%9}, {%0,%1,%2,%3};"
        : "+f"(d[0]), "+f"(d[1]), "+f"(d[2]), "+f"(d[3])
        : "r"(a[0]), "r"(a[1]), "r"(a[2]), "r"(a[3]), "r"(b0), "r"(b1));
}

// SW128 swizzle address within a tile of 128-byte rows
__device__ __forceinline__ uint32_t swaddr(uint32_t tilebase, int row, int cbyte) {
    uint32_t off = ((uint32_t)(row >> 3) << 10) + ((uint32_t)(row & 7) << 7)
                 + (uint32_t)cbyte;
    return tilebase + (off ^ ((off >> 3) & 0x70u));
}

// ---------------------------------------------------------------------------
// Converters (batched over slabs)
// ---------------------------------------------------------------------------
// fp32 -> fp16, 3 sources -> 3 slabs of g_A16
__global__ __launch_bounds__(256)
void conv_a_all(const float* __restrict__ X0, const float* __restrict__ X1,
                const float* __restrict__ X2, __half* __restrict__ Y)
{
    const int slab = blockIdx.y;
    const float* X = (slab == 0) ? X0 : (slab == 1) ? X1 : X2;
    const size_t i = ((size_t)blockIdx.x * 256 + threadIdx.x) * 4;
    float4 v = *(const float4*)(X + i);
    unsigned short h[4];
    #pragma unroll
    for (int e = 0; e < 4; e++)
        h[e] = __half_as_ushort(__float2half_rn((&v.x)[e]));
    uint2 u;
    u.x = (uint32_t)h[0] | ((uint32_t)h[1] << 16);
    u.y = (uint32_t)h[2] | ((uint32_t)h[3] << 16);
    *(uint2*)(Y + (size_t)slab * M_ * DM + i) = u;
}

// W [K,N] fp32 -> transposed [N,K] fp16, 4 slabs
__global__ __launch_bounds__(256)
void conv_w_all(const float* __restrict__ W0, const float* __restrict__ W1,
                const float* __restrict__ W2, const float* __restrict__ W3,
                __half* __restrict__ Y)
{
    __shared__ float s[32][33];
    const int slab = blockIdx.z;
    const float* W = (slab == 0) ? W0 : (slab == 1) ? W1 : (slab == 2) ? W2 : W3;
    __half* Yo = Y + (size_t)slab * DM * DM;
    const int n0 = blockIdx.x * 32, k0 = blockIdx.y * 32;
    const int tx = threadIdx.x & 31, ty = threadIdx.x >> 5;  // 32 x 8
    #pragma unroll
    for (int i = 0; i < 4; i++)
        s[ty + i * 8][tx] = W[(size_t)(k0 + ty + i * 8) * DM + n0 + tx];
    __syncthreads();
    #pragma unroll
    for (int i = 0; i < 4; i++) {
        float x = s[tx][ty + i * 8];
        Yo[(size_t)(n0 + ty + i * 8) * DM + k0 + tx] = __float2half_rn(x);
    }
}

// ---------------------------------------------------------------------------
// Single-pass fp16 tensor GEMM, batched over blockIdx.z slabs:
//   C_s[M,N] = A16_s[M,K] @ W16_s^T[K,N] + bias_s  (+ optional elu+1)
// CTA 128x256, 8 warps (64x64 warp tile), BK=64, 3-stage cp.async ring.
// ---------------------------------------------------------------------------
__device__ __forceinline__ void load_chunk(
    const __half* A16, const __half* B16,
    size_t aRowBase, int n0, int tid, int ch, uint32_t stg)
{
    const uint32_t kbyte = (uint32_t)ch * (KC * 2);
    // A: 1024 flits (128 rows x 8)
    #pragma unroll
    for (int i = 0; i < 4; i++) {
        const int f = i * 256 + tid;
        const int r = f >> 3, c = f & 7;
        cp16(swaddr(stg, r, c * 16),
             (const char*)A16 + (aRowBase + r) * (DM * 2) + kbyte + c * 16);
    }
    // B: 2048 flits (256 rows x 8)
    #pragma unroll
    for (int i = 0; i < 8; i++) {
        const int f = i * 256 + tid;
        const int r = f >> 3, c = f & 7;
        cp16(swaddr(stg + TLA, r, c * 16),
             (const char*)B16 + (size_t)(n0 + r) * (DM * 2) + kbyte + c * 16);
    }
}

__global__ __launch_bounds__(256, 1)
void gemm_tc_kernel(const __half* __restrict__ A16,
                    const __half* __restrict__ W16,
                    const float* __restrict__ b0, const float* __restrict__ b1,
                    const float* __restrict__ b2,
                    float* __restrict__ C0, float* __restrict__ C1,
                    float* __restrict__ C2,
                    int actmask)
{
    extern __shared__ char smem[];
    const uint32_t sbase = smem_u32(smem);

    const int slab = blockIdx.z;
    const __half* B16 = W16 + (size_t)slab * DM * DM;
    const float* bias = (slab == 0) ? b0 : (slab == 1) ? b1 : b2;
    float* C = (slab == 0) ? C0 : (slab == 1) ? C1 : C2;
    const int act = (actmask >> slab) & 1;

    const int tid  = threadIdx.x;
    const int wid  = tid >> 5, lane = tid & 31;
    const int wr   = wid & 1;          // warp m-row: m offset wr*64
    const int wc   = wid >> 1;         // warp n-col: n offset wc*64
    const int mloc = blockIdx.y * 128;
    const size_t aRowBase = (size_t)slab * M_ + mloc;
    const int n0 = blockIdx.x * 256;

    // ldmatrix lane addressing
    const int q   = lane >> 3;
    const int lr  = lane & 7;
    const int rQ  = (q & 1) * 8 + lr;       // row within 16-row tile
    const int kQ  = (q >> 1) * 16;          // byte offset within k16 (16B half)

    float acc[4][8][4];
    #pragma unroll
    for (int mt = 0; mt < 4; mt++)
        #pragma unroll
        for (int nt = 0; nt < 8; nt++)
            #pragma unroll
            for (int e = 0; e < 4; e++) acc[mt][nt][e] = 0.f;

    // prologue: stages 0,1
    load_chunk(A16, B16, aRowBase, n0, tid, 0, sbase + 0 * STG_B);
    CP_COMMIT();
    load_chunk(A16, B16, aRowBase, n0, tid, 1, sbase + 1 * STG_B);
    CP_COMMIT();

    for (int chk = 0; chk < KCHUNKS; chk++) {
        if (chk + 2 < KCHUNKS)
            load_chunk(A16, B16, aRowBase, n0, tid, chk + 2,
                       sbase + ((chk + 2) % NSTG) * STG_B);
        CP_COMMIT();
        CP_WAIT2();           // groups 0..chk complete
        __syncthreads();

        const uint32_t stg = sbase + (chk % NSTG) * STG_B;
        const uint32_t tA  = stg;
        const uint32_t tB  = stg + TLA;

        #pragma unroll
        for (int k16 = 0; k16 < 4; k16++) {
            const int kb = k16 * 32 + kQ;
            uint32_t Af[4][4], Bf[4][4];
            #pragma unroll
            for (int mt = 0; mt < 4; mt++)
                ldsm4(Af[mt], swaddr(tA, wr * 64 + mt * 16 + rQ, kb));
            #pragma unroll
            for (int g = 0; g < 4; g++)
                ldsm4(Bf[g], swaddr(tB, wc * 64 + g * 16 + rQ, kb));
            #pragma unroll
            for (int mt = 0; mt < 4; mt++)
                #pragma unroll
                for (int g = 0; g < 4; g++)
                    #pragma unroll
                    for (int s = 0; s < 2; s++)
                        mma16816(acc[mt][g * 2 + s], Af[mt], Bf[g][s], Bf[g][s + 2]);
        }
        __syncthreads();   // stage (chk%3) safe to refill at iteration chk+1
    }

    // epilogue
    #pragma unroll
    for (int mt = 0; mt < 4; mt++) {
        const int row = mloc + wr * 64 + mt * 16 + (lane >> 2);
        #pragma unroll
        for (int nt = 0; nt < 8; nt++) {
            const int col = n0 + wc * 64 + nt * 8 + 2 * (lane & 3);
            const float bb0 = bias[col], bb1 = bias[col + 1];
            float v0 = acc[mt][nt][0] + bb0;
            float v1 = acc[mt][nt][1] + bb1;
            float v2 = acc[mt][nt][2] + bb0;
            float v3 = acc[mt][nt][3] + bb1;
            if (act) {
                v0 = (v0 > 0.f) ? (v0 + 1.f) : expf(v0);
                v1 = (v1 > 0.f) ? (v1 + 1.f) : expf(v1);
                v2 = (v2 > 0.f) ? (v2 + 1.f) : expf(v2);
                v3 = (v3 > 0.f) ? (v3 + 1.f) : expf(v3);
            }
            *(float2*)(C + (size_t)row * DM + col)       = make_float2(v0, v1);
            *(float2*)(C + (size_t)(row + 8) * DM + col) = make_float2(v2, v3);
        }
    }
}

// ---------------------------------------------------------------------------
// Chunked linear-attention scan (validated R6/R8-R10); chunk_out emits fp16.
// ---------------------------------------------------------------------------
__global__ __launch_bounds__(256, 2)
void attn_chunk_sums(const float* __restrict__ K,
                     const float* __restrict__ V,
                     float* __restrict__ S,
                     float* __restrict__ Z)
{
    __shared__ float sK[64][64];
    __shared__ float sV[64][64];

    const int ch = blockIdx.x, bh = blockIdx.y;
    const int b = bh >> 4, h = bh & 15;
    const size_t base = (size_t)b * L_ * DM + (size_t)h * HD + (size_t)ch * CH * DM;
    const int tid = threadIdx.x;
    const int tx = tid & 15, ty = tid >> 4;

    #pragma unroll
    for (int it = 0; it < 4; it++) {
        const int r = ty + it * 16;
        *(float4*)&sK[r][tx * 4] = *(const float4*)(K + base + (size_t)r * DM + tx * 4);
        *(float4*)&sV[r][tx * 4] = *(const float4*)(V + base + (size_t)r * DM + tx * 4);
    }
    __syncthreads();

    float acc[4][4];
    #pragma unroll
    for (int i = 0; i < 4; i++)
        #pragma unroll
        for (int j = 0; j < 4; j++) acc[i][j] = 0.f;

    #pragma unroll 4
    for (int j = 0; j < 64; j++) {
        float4 vc = *(const float4*)&sV[j][ty * 4];
        float4 ka = *(const float4*)&sK[j][tx * 4];
        #pragma unroll
        for (int ci = 0; ci < 4; ci++)
            #pragma unroll
            for (int ai = 0; ai < 4; ai++)
                acc[ci][ai] += (&vc.x)[ci] * (&ka.x)[ai];
    }

    float* sout = S + ((size_t)bh * NCH + ch) * (HD * HD);
    #pragma unroll
    for (int ci = 0; ci < 4; ci++)
        *(float4*)(sout + (size_t)(ty * 4 + ci) * HD + tx * 4) =
            make_float4(acc[ci][0], acc[ci][1], acc[ci][2], acc[ci][3]);

    if (tid < 64) {
        float s = 0.f;
        #pragma unroll 8
        for (int j = 0; j < 64; j++) s += sK[j][tid];
        Z[((size_t)bh * NCH + ch) * HD + tid] = s;
    }
}

__global__ __launch_bounds__(512, 1)
void attn_prefix(float* __restrict__ S, float* __restrict__ Z)
{
    const int bh = blockIdx.x;
    const int tid = threadIdx.x;
    const size_t sb = (size_t)bh * NCH * (HD * HD);

    float run[8];
    #pragma unroll
    for (int u = 0; u < 8; u++) run[u] = 0.f;

    for (int ch = 0; ch < NCH; ch++) {
        #pragma unroll
        for (int u = 0; u < 8; u++) {
            const size_t idx = sb + (size_t)ch * (HD * HD) + tid + u * 512;
            float t = S[idx];
            S[idx] = run[u];
            run[u] += t;
        }
    }

    if (tid < 64) {
        const size_t zb = (size_t)bh * NCH * HD;
        float rz = 0.f;
        for (int ch = 0; ch < NCH; ch++) {
            float t = Z[zb + (size_t)ch * HD + tid];
            Z[zb + (size_t)ch * HD + tid] = rz;
            rz += t;
        }
    }
}

__device__ __forceinline__ int skcol(int r, int c) {
    return 4 * (((r >> 2) + c) & 15) + (r & 3);
}

__global__ __launch_bounds__(256, 2)
void attn_chunk_out(const float* __restrict__ Q,
                    const float* __restrict__ K,
                    const float* __restrict__ V,
                    const float* __restrict__ Sp,
                    const float* __restrict__ Zp,
                    __half* __restrict__ O16)
{
    __shared__ float sQT[64][64];
    __shared__ float sKV[64][64];
    __shared__ float sW[64][64];

    const int ch = blockIdx.x, bh = blockIdx.y;
    const int b = bh >> 4, h = bh & 15;
    const size_t base = (size_t)b * L_ * DM + (size_t)h * HD + (size_t)ch * CH * DM;
    const int tid = threadIdx.x;
    const int tx = tid & 15, ty = tid >> 4;

    #pragma unroll
    for (int it = 0; it < 4; it++) {
        const int r = ty + it * 16;
        float4 qv = *(const float4*)(Q + base + (size_t)r * DM + tx * 4);
        float4 vv = *(const float4*)(V + base + (size_t)r * DM + tx * 4);
        #pragma unroll
        for (int u = 0; u < 4; u++) {
            const int c = tx * 4 + u;
            sQT[c][skcol(r, c)] = (&qv.x)[u];
            sKV[c][skcol(r, c)] = (&vv.x)[u];
        }
    }
    __syncthreads();

    {
        float g[4][4];
        #pragma unroll
        for (int i = 0; i < 4; i++)
            #pragma unroll
            for (int j = 0; j < 4; j++) g[i][j] = 0.f;

        #pragma unroll 4
        for (int c = 0; c < 64; c++) {
            float4 qi = *(const float4*)&sQT[c][4 * ((ty + c) & 15)];
            float4 vj = *(const float4*)&sKV[c][4 * ((tx + c) & 15)];
            #pragma unroll
            for (int ii = 0; ii < 4; ii++)
                #pragma unroll
                for (int jj = 0; jj < 4; jj++)
                    g[ii][jj] += (&qi.x)[ii] * (&vj.x)[jj];
        }
        #pragma unroll
        for (int ii = 0; ii < 4; ii++) {
            const int i = ty * 4 + ii;
            #pragma unroll
            for (int jj = 0; jj < 4; jj++) {
                const int j = tx * 4 + jj;
                sW[i][j] = (j <= i) ? g[ii][jj] : 0.f;
            }
        }
    }
    __syncthreads();

    #pragma unroll
    for (int it = 0; it < 4; it++) {
        const int r = ty + it * 16;
        *(float4*)&sKV[r][tx * 4] = *(const float4*)(K + base + (size_t)r * DM + tx * 4);
    }
    __syncthreads();

    float acc[4][4];
    #pragma unroll
    for (int i = 0; i < 4; i++)
        #pragma unroll
        for (int j = 0; j < 4; j++) acc[i][j] = 0.f;

    #pragma unroll 4
    for (int j = 0; j < 64; j++) {
        float gi[4];
        #pragma unroll
        for (int ii = 0; ii < 4; ii++) gi[ii] = sW[ty * 4 + ii][j];
        float4 ka = *(const float4*)&sKV[j][tx * 4];
        #pragma unroll
        for (int ii = 0; ii < 4; ii++)
            #pragma unroll
            for (int aa = 0; aa < 4; aa++)
                acc[ii][aa] += gi[ii] * (&ka.x)[aa];
    }
    __syncthreads();

    {
        const float* sp = Sp + ((size_t)bh * NCH + ch) * (HD * HD);
        #pragma unroll
        for (int it = 0; it < 4; it++) {
            const int r = ty + it * 16;
            *(float4*)&sW[r][tx * 4] = *(const float4*)(sp + (size_t)r * HD + tx * 4);
        }
    }
    __syncthreads();

    #pragma unroll 4
    for (int c = 0; c < 64; c++) {
        float4 qi = *(const float4*)&sQT[c][4 * ((ty + c) & 15)];
        float4 sa = *(const float4*)&sW[c][tx * 4];
        #pragma unroll
        for (int ii = 0; ii < 4; ii++)
            #pragma unroll
            for (int aa = 0; aa < 4; aa++)
                acc[ii][aa] += (&qi.x)[ii] * (&sa.x)[aa];
    }
    __syncthreads();

    if (tid < 64) {
        const int a = tid;
        float run = Zp[((size_t)bh * NCH + ch) * HD + a];
        for (int i = 0; i < 64; i++) {
            run += sKV[i][a];
            sW[i][a] = run;
        }
    }
    __syncthreads();

    #pragma unroll
    for (int ii = 0; ii < 4; ii++) {
        const int i = ty * 4 + ii;
        float4 z = *(const float4*)&sW[i][tx * 4];
        unsigned short o[4];
        #pragma unroll
        for (int aa = 0; aa < 4; aa++) {
            const int a = tx * 4 + aa;
            const float qv = sQT[a][skcol(i, a)];
            o[aa] = __half_as_ushort(
                __float2half_rn(acc[ii][aa] / (qv * (&z.x)[aa] + EPSC)));
        }
        uint2 u;
        u.x = (uint32_t)o[0] | ((uint32_t)o[1] << 16);
        u.y = (uint32_t)o[2] | ((uint32_t)o[3] << 16);
        *(uint2*)(O16 + base + (size_t)i * DM + tx * 4) = u;
    }
}

// ---------------------------------------------------------------------------
// kernel_launch
// ---------------------------------------------------------------------------
extern "C" void kernel_launch(void* const* d_in, const int* in_sizes, int n_in,
                              void* d_out, int out_size)
{
    const float* queries = (const float*)d_in[0];
    const float* keys    = (const float*)d_in[1];
    const float* values  = (const float*)d_in[2];
    const float* Wq = (const float*)d_in[3];
    const float* bq = (const float*)d_in[4];
    const float* Wk = (const float*)d_in[5];
    const float* bk = (const float*)d_in[6];
    const float* Wv = (const float*)d_in[7];
    const float* bv = (const float*)d_in[8];
    const float* Wo = (const float*)d_in[9];
    const float* bo = (const float*)d_in[10];
    float* out = (float*)d_out;

    float *pQ, *pK, *pV, *pS, *pZ;
    __half *pA16, *pW16;
    cudaGetSymbolAddress((void**)&pQ, g_Q);
    cudaGetSymbolAddress((void**)&pK, g_K);
    cudaGetSymbolAddress((void**)&pV, g_V);
    cudaGetSymbolAddress((void**)&pS, g_S);
    cudaGetSymbolAddress((void**)&pZ, g_Z);
    cudaGetSymbolAddress((void**)&pA16, g_A16);
    cudaGetSymbolAddress((void**)&pW16, g_W16);

    cudaFuncSetAttribute(gemm_tc_kernel,
                         cudaFuncAttributeMaxDynamicSharedMemorySize, SMEM_GEMM);

    // 1) all weight converts (independent of everything else)
    conv_w_all<<<dim3(DM / 32, DM / 32, 4), 256>>>(Wq, Wk, Wv, Wo, pW16);
    // 2) all input converts
    conv_a_all<<<dim3(M_ * DM / 1024, 3), 256>>>(queries, keys, values, pA16);
    // 3) batched projection GEMM (slabs q,k,v; act on q,k)
    gemm_tc_kernel<<<dim3(DM / 256, M_ / 128, 3), 256, SMEM_GEMM>>>(
        pA16, pW16, bq, bk, bv, pQ, pK, pV, 0b011);
    // 4) chunked causal linear attention; writes fp16 into A16 slab 0
    {
        dim3 chunk_grid(NCH, B_ * H_);
        attn_chunk_sums<<<chunk_grid, 256>>>(pK, pV, pS, pZ);
        attn_prefix<<<B_ * H_, 512>>>(pS, pZ);
        attn_chunk_out<<<chunk_grid, 256>>>(pQ, pK, pV, pS, pZ, pA16);
    }
    // 5) output projection (W slab 3)
    gemm_tc_kernel<<<dim3(DM / 256, M_ / 128, 1), 256, SMEM_GEMM>>>(
        pA16, pW16 + (size_t)3 * DM * DM, bo, bo, bo, out, out, out, 0);
}

// round 12
// speedup vs baseline: 1.1034x; 1.1034x over previous
#include <cuda_runtime.h>
#include <cuda_fp16.h>
#include <cstdint>
#include <math.h>

// Problem constants
#define B_   4
#define L_   2048
#define DM   1024
#define H_   16
#define HD   64
#define M_   (B_ * L_)       // 8192 rows
#define EPSC 1e-6f
#define CH   64              // scan chunk length
#define NCH  (L_ / CH)       // 32 chunks

// GEMM constants (R10-validated shape): CTA 128x128, warp tile 32x64, BK=64
#define KC        64                  // fp16 K elems per chunk (128 B rows)
#define KCHUNKS   (DM / KC)           // 16
#define TILE_B    16384               // 128-row x 128-byte tile
#define STG_B     (2 * TILE_B)        // A, B  = 32 KB
#define NSTG      3
#define SMEM_GEMM (NSTG * STG_B)      // 96 KB, occ 2

// ---------------------------------------------------------------------------
// Scratch (allocation-free rule: __device__ globals)
// ---------------------------------------------------------------------------
__device__ float g_Q[(size_t)M_ * DM];
__device__ float g_K[(size_t)M_ * DM];
__device__ float g_V[(size_t)M_ * DM];
__device__ float g_S[(size_t)B_ * H_ * NCH * HD * HD]; // chunk S sums -> prefix
__device__ float g_Z[(size_t)B_ * H_ * NCH * HD];      // chunk Z sums -> prefix
__device__ __half g_A16[(size_t)3 * M_ * DM];          // fp16 A, 3 slabs (q,k,v / attn)
__device__ __half g_W16[(size_t)4 * DM * DM];          // [N,K] fp16, 4 slabs (q,k,v,o)

// ---------------------------------------------------------------------------
// PTX helpers (base-target sm_103-safe: cp.async, ldmatrix, mma.sync only)
// ---------------------------------------------------------------------------
__device__ __forceinline__ uint32_t smem_u32(const void* p) {
    uint32_t a;
    asm("{ .reg .u64 t; cvta.to.shared.u64 t, %1; cvt.u32.u64 %0, t; }" : "=r"(a) : "l"(p));
    return a;
}
__device__ __forceinline__ void cp16(uint32_t saddr, const void* g) {
    asm volatile("cp.async.cg.shared.global [%0], [%1], 16;\n" :: "r"(saddr), "l"(g));
}
#define CP_COMMIT() asm volatile("cp.async.commit_group;\n")
#define CP_WAIT1()  asm volatile("cp.async.wait_group 1;\n")

__device__ __forceinline__ void ldsm4(uint32_t* r, uint32_t addr) {
    asm volatile("ldmatrix.sync.aligned.m8n8.x4.shared.b16 {%0,%1,%2,%3}, [%4];"
                 : "=r"(r[0]), "=r"(r[1]), "=r"(r[2]), "=r"(r[3]) : "r"(addr));
}
__device__ __forceinline__ void mma16816(float* d, const uint32_t* a,
                                         uint32_t b0, uint32_t b1) {
    asm volatile(
        "mma.sync.aligned.m16n8k16.row.col.f32.f16.f16.f32 "
        "{%0,%1,%2,%3}, {%4,%5,%6,%7}, {%8,%9}, {%0,%1,%2,%3};"
        : "+f"(d[0]), "+f"(d[1]), "+f"(d[2]), "+f"(d[3])
        : "r"(a[0]), "r"(a[1]), "r"(a[2]), "r"(a[3]), "r"(b0), "r"(b1));
}

// SW128 swizzle address within a 128-row x 128-byte tile
__device__ __forceinline__ uint32_t swaddr(uint32_t tilebase, int row, int cbyte) {
    uint32_t off = ((uint32_t)(row >> 3) << 10) + ((uint32_t)(row & 7) << 7)
                 + (uint32_t)cbyte;
    return tilebase + (off ^ ((off >> 3) & 0x70u));
}

// ---------------------------------------------------------------------------
// Converters (batched over slabs)
// ---------------------------------------------------------------------------
__global__ __launch_bounds__(256)
void conv_a_all(const float* __restrict__ X0, const float* __restrict__ X1,
                const float* __restrict__ X2, __half* __restrict__ Y)
{
    const int slab = blockIdx.y;
    const float* X = (slab == 0) ? X0 : (slab == 1) ? X1 : X2;
    const size_t i = ((size_t)blockIdx.x * 256 + threadIdx.x) * 4;
    float4 v = *(const float4*)(X + i);
    unsigned short h[4];
    #pragma unroll
    for (int e = 0; e < 4; e++)
        h[e] = __half_as_ushort(__float2half_rn((&v.x)[e]));
    uint2 u;
    u.x = (uint32_t)h[0] | ((uint32_t)h[1] << 16);
    u.y = (uint32_t)h[2] | ((uint32_t)h[3] << 16);
    *(uint2*)(Y + (size_t)slab * M_ * DM + i) = u;
}

// W [K,N] fp32 -> transposed [N,K] fp16, 4 slabs
__global__ __launch_bounds__(256)
void conv_w_all(const float* __restrict__ W0, const float* __restrict__ W1,
                const float* __restrict__ W2, const float* __restrict__ W3,
                __half* __restrict__ Y)
{
    __shared__ float s[32][33];
    const int slab = blockIdx.z;
    const float* W = (slab == 0) ? W0 : (slab == 1) ? W1 : (slab == 2) ? W2 : W3;
    __half* Yo = Y + (size_t)slab * DM * DM;
    const int n0 = blockIdx.x * 32, k0 = blockIdx.y * 32;
    const int tx = threadIdx.x & 31, ty = threadIdx.x >> 5;  // 32 x 8
    #pragma unroll
    for (int i = 0; i < 4; i++)
        s[ty + i * 8][tx] = W[(size_t)(k0 + ty + i * 8) * DM + n0 + tx];
    __syncthreads();
    #pragma unroll
    for (int i = 0; i < 4; i++) {
        float x = s[tx][ty + i * 8];
        Yo[(size_t)(n0 + ty + i * 8) * DM + k0 + tx] = __float2half_rn(x);
    }
}

// ---------------------------------------------------------------------------
// Single-pass fp16 tensor GEMM (R10 shape), batched over blockIdx.z slabs.
//   C_s[M,N] = A16_s[M,K] @ W16_s^T[K,N] + bias_s  (+ optional elu+1)
// CTA 128x128, 8 warps (32x64 warp tile), BK=64, 3-stage ring, ONE sync/chunk.
// ---------------------------------------------------------------------------
__device__ __forceinline__ void load_chunk(
    const __half* A16, const __half* B16,
    size_t aRowBase, int n0, int tid, int ch, uint32_t stg)
{
    const int r0 = tid >> 3;          // 0..31
    const int c  = tid & 7;           // 16B flit within 128B row
    const uint32_t kbyte = (uint32_t)ch * (KC * 2);
    #pragma unroll
    for (int i = 0; i < 4; i++) {
        const int r = r0 + 32 * i;
        const uint32_t sw = swaddr(0, r, c * 16);
        cp16(stg + 0 * TILE_B + sw,
             (const char*)A16 + (aRowBase + r) * (DM * 2) + kbyte + c * 16);
        cp16(stg + 1 * TILE_B + sw,
             (const char*)B16 + (size_t)(n0 + r) * (DM * 2) + kbyte + c * 16);
    }
}

__global__ __launch_bounds__(256, 2)
void gemm_tc_kernel(const __half* __restrict__ A16,
                    const __half* __restrict__ W16,
                    const float* __restrict__ b0, const float* __restrict__ b1,
                    const float* __restrict__ b2,
                    float* __restrict__ C0, float* __restrict__ C1,
                    float* __restrict__ C2,
                    int actmask)
{
    extern __shared__ char smem[];
    const uint32_t sbase = smem_u32(smem);

    const int slab = blockIdx.z;
    const __half* B16 = W16 + (size_t)slab * DM * DM;
    const float* bias = (slab == 0) ? b0 : (slab == 1) ? b1 : b2;
    float* C = (slab == 0) ? C0 : (slab == 1) ? C1 : C2;
    const int act = (actmask >> slab) & 1;

    const int tid  = threadIdx.x;
    const int wid  = tid >> 5, lane = tid & 31;
    const int wr   = wid & 3;          // warp m-row: m offset wr*32
    const int wc   = wid >> 2;         // warp n-col: n offset wc*64
    const int m0 = blockIdx.y * 128;
    const size_t aRowBase = (size_t)slab * M_ + m0;
    const int n0 = blockIdx.x * 128;

    // ldmatrix lane addressing
    const int q   = lane >> 3;
    const int lr  = lane & 7;
    const int rQ  = (q & 1) * 8 + lr;       // row within 16-row tile
    const int kQ  = (q >> 1) * 16;          // byte offset within k16 (16B half)

    float acc[2][8][4];
    #pragma unroll
    for (int mt = 0; mt < 2; mt++)
        #pragma unroll
        for (int nt = 0; nt < 8; nt++)
            #pragma unroll
            for (int e = 0; e < 4; e++) acc[mt][nt][e] = 0.f;

    // prologue: stages 0,1
    load_chunk(A16, B16, aRowBase, n0, tid, 0, sbase + 0 * STG_B);
    CP_COMMIT();
    load_chunk(A16, B16, aRowBase, n0, tid, 1, sbase + 1 * STG_B);
    CP_COMMIT();

    for (int chk = 0; chk < KCHUNKS; chk++) {
        CP_WAIT1();           // chunk chk's loads complete (<=1 group in flight)
        __syncthreads();      // publish; all warps past compute of chk-1

        // refill stage (chk+2)%3 — its last readers were chunk chk-1, done by
        // the barrier above. Single sync per chunk.
        if (chk + 2 < KCHUNKS)
            load_chunk(A16, B16, aRowBase, n0, tid, chk + 2,
                       sbase + ((chk + 2) % NSTG) * STG_B);
        CP_COMMIT();          // uniform commit keeps group counts aligned

        const uint32_t stg = sbase + (chk % NSTG) * STG_B;
        const uint32_t tA  = stg + 0 * TILE_B;
        const uint32_t tB  = stg + 1 * TILE_B;

        #pragma unroll
        for (int k16 = 0; k16 < 4; k16++) {
            const int kb = k16 * 32 + kQ;
            uint32_t Af[2][4];
            #pragma unroll
            for (int mt = 0; mt < 2; mt++)
                ldsm4(Af[mt], swaddr(tA, wr * 32 + mt * 16 + rQ, kb));
            #pragma unroll
            for (int g = 0; g < 4; g++) {
                uint32_t Bf[4];
                ldsm4(Bf, swaddr(tB, wc * 64 + g * 16 + rQ, kb));
                #pragma unroll
                for (int s = 0; s < 2; s++) {
                    const int nt = g * 2 + s;
                    #pragma unroll
                    for (int mt = 0; mt < 2; mt++)
                        mma16816(acc[mt][nt], Af[mt], Bf[s], Bf[s + 2]);
                }
            }
        }
    }

    // epilogue
    #pragma unroll
    for (int mt = 0; mt < 2; mt++) {
        const int row = m0 + wr * 32 + mt * 16 + (lane >> 2);
        #pragma unroll
        for (int nt = 0; nt < 8; nt++) {
            const int col = n0 + wc * 64 + nt * 8 + 2 * (lane & 3);
            const float bb0 = bias[col], bb1 = bias[col + 1];
            float v0 = acc[mt][nt][0] + bb0;
            float v1 = acc[mt][nt][1] + bb1;
            float v2 = acc[mt][nt][2] + bb0;
            float v3 = acc[mt][nt][3] + bb1;
            if (act) {
                v0 = (v0 > 0.f) ? (v0 + 1.f) : expf(v0);
                v1 = (v1 > 0.f) ? (v1 + 1.f) : expf(v1);
                v2 = (v2 > 0.f) ? (v2 + 1.f) : expf(v2);
                v3 = (v3 > 0.f) ? (v3 + 1.f) : expf(v3);
            }
            *(float2*)(C + (size_t)row * DM + col)       = make_float2(v0, v1);
            *(float2*)(C + (size_t)(row + 8) * DM + col) = make_float2(v2, v3);
        }
    }
}

// ---------------------------------------------------------------------------
// Chunked linear-attention scan; chunk_out emits fp16 into A16 slab 0.
// ---------------------------------------------------------------------------
__global__ __launch_bounds__(256, 2)
void attn_chunk_sums(const float* __restrict__ K,
                     const float* __restrict__ V,
                     float* __restrict__ S,
                     float* __restrict__ Z)
{
    __shared__ float sK[64][64];
    __shared__ float sV[64][64];

    const int ch = blockIdx.x, bh = blockIdx.y;
    const int b = bh >> 4, h = bh & 15;
    const size_t base = (size_t)b * L_ * DM + (size_t)h * HD + (size_t)ch * CH * DM;
    const int tid = threadIdx.x;
    const int tx = tid & 15, ty = tid >> 4;

    #pragma unroll
    for (int it = 0; it < 4; it++) {
        const int r = ty + it * 16;
        *(float4*)&sK[r][tx * 4] = *(const float4*)(K + base + (size_t)r * DM + tx * 4);
        *(float4*)&sV[r][tx * 4] = *(const float4*)(V + base + (size_t)r * DM + tx * 4);
    }
    __syncthreads();

    float acc[4][4];
    #pragma unroll
    for (int i = 0; i < 4; i++)
        #pragma unroll
        for (int j = 0; j < 4; j++) acc[i][j] = 0.f;

    #pragma unroll 4
    for (int j = 0; j < 64; j++) {
        float4 vc = *(const float4*)&sV[j][ty * 4];
        float4 ka = *(const float4*)&sK[j][tx * 4];
        #pragma unroll
        for (int ci = 0; ci < 4; ci++)
            #pragma unroll
            for (int ai = 0; ai < 4; ai++)
                acc[ci][ai] += (&vc.x)[ci] * (&ka.x)[ai];
    }

    float* sout = S + ((size_t)bh * NCH + ch) * (HD * HD);
    #pragma unroll
    for (int ci = 0; ci < 4; ci++)
        *(float4*)(sout + (size_t)(ty * 4 + ci) * HD + tx * 4) =
            make_float4(acc[ci][0], acc[ci][1], acc[ci][2], acc[ci][3]);

    if (tid < 64) {
        float s = 0.f;
        #pragma unroll 8
        for (int j = 0; j < 64; j++) s += sK[j][tid];
        Z[((size_t)bh * NCH + ch) * HD + tid] = s;
    }
}

__global__ __launch_bounds__(512, 1)
void attn_prefix(float* __restrict__ S, float* __restrict__ Z)
{
    const int bh = blockIdx.x;
    const int tid = threadIdx.x;
    const size_t sb = (size_t)bh * NCH * (HD * HD);

    float run[8];
    #pragma unroll
    for (int u = 0; u < 8; u++) run[u] = 0.f;

    for (int ch = 0; ch < NCH; ch++) {
        #pragma unroll
        for (int u = 0; u < 8; u++) {
            const size_t idx = sb + (size_t)ch * (HD * HD) + tid + u * 512;
            float t = S[idx];
            S[idx] = run[u];
            run[u] += t;
        }
    }

    if (tid < 64) {
        const size_t zb = (size_t)bh * NCH * HD;
        float rz = 0.f;
        for (int ch = 0; ch < NCH; ch++) {
            float t = Z[zb + (size_t)ch * HD + tid];
            Z[zb + (size_t)ch * HD + tid] = rz;
            rz += t;
        }
    }
}

__device__ __forceinline__ int skcol(int r, int c) {
    return 4 * (((r >> 2) + c) & 15) + (r & 3);
}

__global__ __launch_bounds__(256, 2)
void attn_chunk_out(const float* __restrict__ Q,
                    const float* __restrict__ K,
                    const float* __restrict__ V,
                    const float* __restrict__ Sp,
                    const float* __restrict__ Zp,
                    __half* __restrict__ O16)
{
    __shared__ float sQT[64][64];
    __shared__ float sKV[64][64];
    __shared__ float sW[64][64];
    __shared__ float sPart[4][64];

    const int ch = blockIdx.x, bh = blockIdx.y;
    const int b = bh >> 4, h = bh & 15;
    const size_t base = (size_t)b * L_ * DM + (size_t)h * HD + (size_t)ch * CH * DM;
    const int tid = threadIdx.x;
    const int tx = tid & 15, ty = tid >> 4;

    #pragma unroll
    for (int it = 0; it < 4; it++) {
        const int r = ty + it * 16;
        float4 qv = *(const float4*)(Q + base + (size_t)r * DM + tx * 4);
        float4 vv = *(const float4*)(V + base + (size_t)r * DM + tx * 4);
        #pragma unroll
        for (int u = 0; u < 4; u++) {
            const int c = tx * 4 + u;
            sQT[c][skcol(r, c)] = (&qv.x)[u];
            sKV[c][skcol(r, c)] = (&vv.x)[u];
        }
    }
    __syncthreads();

    // Phase A: G[i][j] = q_i . v_j, masked j<=i, into sW
    {
        float g[4][4];
        #pragma unroll
        for (int i = 0; i < 4; i++)
            #pragma unroll
            for (int j = 0; j < 4; j++) g[i][j] = 0.f;

        #pragma unroll 4
        for (int c = 0; c < 64; c++) {
            float4 qi = *(const float4*)&sQT[c][4 * ((ty + c) & 15)];
            float4 vj = *(const float4*)&sKV[c][4 * ((tx + c) & 15)];
            #pragma unroll
            for (int ii = 0; ii < 4; ii++)
                #pragma unroll
                for (int jj = 0; jj < 4; jj++)
                    g[ii][jj] += (&qi.x)[ii] * (&vj.x)[jj];
        }
        #pragma unroll
        for (int ii = 0; ii < 4; ii++) {
            const int i = ty * 4 + ii;
            #pragma unroll
            for (int jj = 0; jj < 4; jj++) {
                const int j = tx * 4 + jj;
                sW[i][j] = (j <= i) ? g[ii][jj] : 0.f;
            }
        }
    }
    __syncthreads();

    // reload K row-major into sKV
    #pragma unroll
    for (int it = 0; it < 4; it++) {
        const int r = ty + it * 16;
        *(float4*)&sKV[r][tx * 4] = *(const float4*)(K + base + (size_t)r * DM + tx * 4);
    }
    __syncthreads();

    // Phase B: num += G @ K
    float acc[4][4];
    #pragma unroll
    for (int i = 0; i < 4; i++)
        #pragma unroll
        for (int j = 0; j < 4; j++) acc[i][j] = 0.f;

    #pragma unroll 4
    for (int j = 0; j < 64; j++) {
        float gi[4];
        #pragma unroll
        for (int ii = 0; ii < 4; ii++) gi[ii] = sW[ty * 4 + ii][j];
        float4 ka = *(const float4*)&sKV[j][tx * 4];
        #pragma unroll
        for (int ii = 0; ii < 4; ii++)
            #pragma unroll
            for (int aa = 0; aa < 4; aa++)
                acc[ii][aa] += gi[ii] * (&ka.x)[aa];
    }
    __syncthreads();

    // load exclusive-prefix S into sW
    {
        const float* sp = Sp + ((size_t)bh * NCH + ch) * (HD * HD);
        #pragma unroll
        for (int it = 0; it < 4; it++) {
            const int r = ty + it * 16;
            *(float4*)&sW[r][tx * 4] = *(const float4*)(sp + (size_t)r * HD + tx * 4);
        }
    }
    __syncthreads();

    // Phase C: num += Q @ Sprev
    #pragma unroll 4
    for (int c = 0; c < 64; c++) {
        float4 qi = *(const float4*)&sQT[c][4 * ((ty + c) & 15)];
        float4 sa = *(const float4*)&sW[c][tx * 4];
        #pragma unroll
        for (int ii = 0; ii < 4; ii++)
            #pragma unroll
            for (int aa = 0; aa < 4; aa++)
                acc[ii][aa] += (&qi.x)[ii] * (&sa.x)[aa];
    }
    __syncthreads();

    // Phase D (parallel segmented scan): sW[i][a] = Zp[a] + cumsum_{j<=i} K[j][a]
    {
        const int a = tid & 63, seg = tid >> 6;   // 4 segments x 16 rows
        float s16 = 0.f;
        #pragma unroll
        for (int i = 0; i < 16; i++) s16 += sKV[seg * 16 + i][a];
        sPart[seg][a] = s16;
        __syncthreads();
        float run = Zp[((size_t)bh * NCH + ch) * HD + a];
        #pragma unroll
        for (int s2 = 0; s2 < 3; s2++)
            if (s2 < seg) run += sPart[s2][a];
        #pragma unroll
        for (int i = 0; i < 16; i++) {
            run += sKV[seg * 16 + i][a];
            sW[seg * 16 + i][a] = run;
        }
    }
    __syncthreads();

    // Phase E: out = num / (q * Z + eps), fp16 store
    #pragma unroll
    for (int ii = 0; ii < 4; ii++) {
        const int i = ty * 4 + ii;
        float4 z = *(const float4*)&sW[i][tx * 4];
        unsigned short o[4];
        #pragma unroll
        for (int aa = 0; aa < 4; aa++) {
            const int a = tx * 4 + aa;
            const float qv = sQT[a][skcol(i, a)];
            o[aa] = __half_as_ushort(
                __float2half_rn(acc[ii][aa] / (qv * (&z.x)[aa] + EPSC)));
        }
        uint2 u;
        u.x = (uint32_t)o[0] | ((uint32_t)o[1] << 16);
        u.y = (uint32_t)o[2] | ((uint32_t)o[3] << 16);
        *(uint2*)(O16 + base + (size_t)i * DM + tx * 4) = u;
    }
}

// ---------------------------------------------------------------------------
// kernel_launch
// ---------------------------------------------------------------------------
extern "C" void kernel_launch(void* const* d_in, const int* in_sizes, int n_in,
                              void* d_out, int out_size)
{
    const float* queries = (const float*)d_in[0];
    const float* keys    = (const float*)d_in[1];
    const float* values  = (const float*)d_in[2];
    const float* Wq = (const float*)d_in[3];
    const float* bq = (const float*)d_in[4];
    const float* Wk = (const float*)d_in[5];
    const float* bk = (const float*)d_in[6];
    const float* Wv = (const float*)d_in[7];
    const float* bv = (const float*)d_in[8];
    const float* Wo = (const float*)d_in[9];
    const float* bo = (const float*)d_in[10];
    float* out = (float*)d_out;

    float *pQ, *pK, *pV, *pS, *pZ;
    __half *pA16, *pW16;
    cudaGetSymbolAddress((void**)&pQ, g_Q);
    cudaGetSymbolAddress((void**)&pK, g_K);
    cudaGetSymbolAddress((void**)&pV, g_V);
    cudaGetSymbolAddress((void**)&pS, g_S);
    cudaGetSymbolAddress((void**)&pZ, g_Z);
    cudaGetSymbolAddress((void**)&pA16, g_A16);
    cudaGetSymbolAddress((void**)&pW16, g_W16);

    cudaFuncSetAttribute(gemm_tc_kernel,
                         cudaFuncAttributeMaxDynamicSharedMemorySize, SMEM_GEMM);

    // 1) all weight converts
    conv_w_all<<<dim3(DM / 32, DM / 32, 4), 256>>>(Wq, Wk, Wv, Wo, pW16);
    // 2) all input converts
    conv_a_all<<<dim3(M_ * DM / 1024, 3), 256>>>(queries, keys, values, pA16);
    // 3) batched projection GEMM (slabs q,k,v; act on q,k)
    gemm_tc_kernel<<<dim3(DM / 128, M_ / 128, 3), 256, SMEM_GEMM>>>(
        pA16, pW16, bq, bk, bv, pQ, pK, pV, 0b011);
    // 4) chunked causal linear attention; writes fp16 into A16 slab 0
    {
        dim3 chunk_grid(NCH, B_ * H_);
        attn_chunk_sums<<<chunk_grid, 256>>>(pK, pV, pS, pZ);
        attn_prefix<<<B_ * H_, 512>>>(pS, pZ);
        attn_chunk_out<<<chunk_grid, 256>>>(pQ, pK, pV, pS, pZ, pA16);
    }
    // 5) output projection (W slab 3, A slab 0)
    gemm_tc_kernel<<<dim3(DM / 128, M_ / 128, 1), 256, SMEM_GEMM>>>(
        pA16, pW16 + (size_t)3 * DM * DM, bo, bo, bo, out, out, out, 0);
}

// round 13
// speedup vs baseline: 1.4835x; 1.3445x over previous
#include <cuda_runtime.h>
#include <cuda_fp16.h>
#include <cstdint>
#include <math.h>

// Problem constants
#define B_   4
#define L_   2048
#define DM   1024
#define H_   16
#define HD   64
#define M_   (B_ * L_)       // 8192 rows
#define EPSC 1e-6f
#define CH   64              // scan chunk length
#define NCH  (L_ / CH)       // 32 chunks

// GEMM constants (validated shape): CTA 128x128, warp tile 32x64, BK=64
#define KC        64
#define KCHUNKS   (DM / KC)           // 16
#define TILE_B    16384               // 128-row x 128-byte tile
#define STG_B     (2 * TILE_B)        // 32 KB
#define NSTG      3
#define SMEM_GEMM (NSTG * STG_B)      // 96 KB, occ 2

// chunk_out dynamic smem layout (bytes)
#define CO_Q    0
#define CO_V    8192
#define CO_K    16384
#define CO_SP   24576
#define CO_NUM  32768                       // float [64][72]
#define CO_ZW   (CO_NUM + 64 * 72 * 4)      // 51200: float [64][64]
#define CO_RED  (CO_ZW + 64 * 64 * 4)       // 67584: float [2][16][68]
#define CO_PART (CO_RED + 2 * 16 * 68 * 4)  // 76288: float [4][64]
#define CO_SMEM (CO_PART + 4 * 64 * 4)      // 77312

// ---------------------------------------------------------------------------
// Scratch (allocation-free rule: __device__ globals)
// ---------------------------------------------------------------------------
__device__ float  g_S[(size_t)B_ * H_ * NCH * HD * HD]; // chunk S sums -> prefix
__device__ float  g_Z[(size_t)B_ * H_ * NCH * HD];      // chunk Z sums -> prefix
__device__ __half g_A16[(size_t)3 * M_ * DM];           // fp16 A slabs (in / attn out)
__device__ __half g_W16[(size_t)4 * DM * DM];           // [N,K] fp16, 4 slabs
__device__ __half g_Q16[(size_t)M_ * DM];
__device__ __half g_K16[(size_t)M_ * DM];
__device__ __half g_V16[(size_t)M_ * DM];

// ---------------------------------------------------------------------------
// PTX helpers (base-target sm_103-safe)
// ---------------------------------------------------------------------------
__device__ __forceinline__ uint32_t smem_u32(const void* p) {
    uint32_t a;
    asm("{ .reg .u64 t; cvta.to.shared.u64 t, %1; cvt.u32.u64 %0, t; }" : "=r"(a) : "l"(p));
    return a;
}
__device__ __forceinline__ void cp16(uint32_t saddr, const void* g) {
    asm volatile("cp.async.cg.shared.global [%0], [%1], 16;\n" :: "r"(saddr), "l"(g));
}
#define CP_COMMIT() asm volatile("cp.async.commit_group;\n")
#define CP_WAIT1()  asm volatile("cp.async.wait_group 1;\n")

__device__ __forceinline__ void ldsm4(uint32_t* r, uint32_t addr) {
    asm volatile("ldmatrix.sync.aligned.m8n8.x4.shared.b16 {%0,%1,%2,%3}, [%4];"
                 : "=r"(r[0]), "=r"(r[1]), "=r"(r[2]), "=r"(r[3]) : "r"(addr));
}
__device__ __forceinline__ void ldsm4t(uint32_t* r, uint32_t addr) {
    asm volatile("ldmatrix.sync.aligned.m8n8.x4.trans.shared.b16 {%0,%1,%2,%3}, [%4];"
                 : "=r"(r[0]), "=r"(r[1]), "=r"(r[2]), "=r"(r[3]) : "r"(addr));
}
__device__ __forceinline__ void mma16816(float* d, const uint32_t* a,
                                         uint32_t b0, uint32_t b1) {
    asm volatile(
        "mma.sync.aligned.m16n8k16.row.col.f32.f16.f16.f32 "
        "{%0,%1,%2,%3}, {%4,%5,%6,%7}, {%8,%9}, {%0,%1,%2,%3};"
        : "+f"(d[0]), "+f"(d[1]), "+f"(d[2]), "+f"(d[3])
        : "r"(a[0]), "r"(a[1]), "r"(a[2]), "r"(a[3]), "r"(b0), "r"(b1));
}
__device__ __forceinline__ uint32_t pack2(float lo, float hi) {
    uint32_t d;
    asm("cvt.rn.f16x2.f32 %0, %1, %2;" : "=r"(d) : "f"(hi), "f"(lo));
    return d;
}

// SW128 swizzle within a tile of 128-byte rows
__device__ __forceinline__ uint32_t swaddr(uint32_t tilebase, int row, int cbyte) {
    uint32_t off = ((uint32_t)(row >> 3) << 10) + ((uint32_t)(row & 7) << 7)
                 + (uint32_t)cbyte;
    return tilebase + (off ^ ((off >> 3) & 0x70u));
}
// Fragment source address: row-major operand [r][k] (16-row x 16-col block)
__device__ __forceinline__ uint32_t naddr(uint32_t tile, int r0, int kb, int q, int lr) {
    return swaddr(tile, r0 + (q & 1) * 8 + lr, kb + (q >> 1) * 16);
}
// Trans fragment: smem holds T[j][col]; want op[m_or_n=col][k=j]
__device__ __forceinline__ uint32_t taddr(uint32_t tile, int j0, int col0, int q, int lr) {
    return swaddr(tile, j0 + (q >> 1) * 8 + lr, (col0 + (q & 1) * 8) * 2);
}

// ---------------------------------------------------------------------------
// Converters (batched)
// ---------------------------------------------------------------------------
__global__ __launch_bounds__(256)
void conv_a_all(const float* __restrict__ X0, const float* __restrict__ X1,
                const float* __restrict__ X2, __half* __restrict__ Y)
{
    const int slab = blockIdx.y;
    const float* X = (slab == 0) ? X0 : (slab == 1) ? X1 : X2;
    const size_t i = ((size_t)blockIdx.x * 256 + threadIdx.x) * 4;
    float4 v = *(const float4*)(X + i);
    uint2 u;
    u.x = pack2(v.x, v.y);
    u.y = pack2(v.z, v.w);
    *(uint2*)(Y + (size_t)slab * M_ * DM + i) = u;
}

__global__ __launch_bounds__(256)
void conv_w_all(const float* __restrict__ W0, const float* __restrict__ W1,
                const float* __restrict__ W2, const float* __restrict__ W3,
                __half* __restrict__ Y)
{
    __shared__ float s[32][33];
    const int slab = blockIdx.z;
    const float* W = (slab == 0) ? W0 : (slab == 1) ? W1 : (slab == 2) ? W2 : W3;
    __half* Yo = Y + (size_t)slab * DM * DM;
    const int n0 = blockIdx.x * 32, k0 = blockIdx.y * 32;
    const int tx = threadIdx.x & 31, ty = threadIdx.x >> 5;
    #pragma unroll
    for (int i = 0; i < 4; i++)
        s[ty + i * 8][tx] = W[(size_t)(k0 + ty + i * 8) * DM + n0 + tx];
    __syncthreads();
    #pragma unroll
    for (int i = 0; i < 4; i++) {
        float x = s[tx][ty + i * 8];
        Yo[(size_t)(n0 + ty + i * 8) * DM + k0 + tx] = __float2half_rn(x);
    }
}

// ---------------------------------------------------------------------------
// fp16 tensor GEMM (R12-validated), fp32 or fp16 output.
// ---------------------------------------------------------------------------
__device__ __forceinline__ void load_chunk(
    const __half* A16, const __half* B16,
    size_t aRowBase, int n0, int tid, int ch, uint32_t stg)
{
    const int r0 = tid >> 3;
    const int c  = tid & 7;
    const uint32_t kbyte = (uint32_t)ch * (KC * 2);
    #pragma unroll
    for (int i = 0; i < 4; i++) {
        const int r = r0 + 32 * i;
        const uint32_t sw = swaddr(0, r, c * 16);
        cp16(stg + 0 * TILE_B + sw,
             (const char*)A16 + (aRowBase + r) * (DM * 2) + kbyte + c * 16);
        cp16(stg + 1 * TILE_B + sw,
             (const char*)B16 + (size_t)(n0 + r) * (DM * 2) + kbyte + c * 16);
    }
}

__global__ __launch_bounds__(256, 2)
void gemm_tc_kernel(const __half* __restrict__ A16,
                    const __half* __restrict__ W16,
                    const float* __restrict__ b0, const float* __restrict__ b1,
                    const float* __restrict__ b2,
                    void* C0v, void* C1v, void* C2v,
                    int actmask, int outhalf)
{
    extern __shared__ char smem[];
    const uint32_t sbase = smem_u32(smem);

    const int slab = blockIdx.z;
    const __half* B16 = W16 + (size_t)slab * DM * DM;
    const float* bias = (slab == 0) ? b0 : (slab == 1) ? b1 : b2;
    void* Cv = (slab == 0) ? C0v : (slab == 1) ? C1v : C2v;
    const int act = (actmask >> slab) & 1;

    const int tid  = threadIdx.x;
    const int wid  = tid >> 5, lane = tid & 31;
    const int wr   = wid & 3;
    const int wc   = wid >> 2;
    const int m0 = blockIdx.y * 128;
    const size_t aRowBase = (size_t)slab * M_ + m0;
    const int n0 = blockIdx.x * 128;

    const int q   = lane >> 3;
    const int lr  = lane & 7;
    const int kQ  = (q >> 1) * 16;

    float acc[2][8][4];
    #pragma unroll
    for (int mt = 0; mt < 2; mt++)
        #pragma unroll
        for (int nt = 0; nt < 8; nt++)
            #pragma unroll
            for (int e = 0; e < 4; e++) acc[mt][nt][e] = 0.f;

    load_chunk(A16, B16, aRowBase, n0, tid, 0, sbase + 0 * STG_B);
    CP_COMMIT();
    load_chunk(A16, B16, aRowBase, n0, tid, 1, sbase + 1 * STG_B);
    CP_COMMIT();

    for (int chk = 0; chk < KCHUNKS; chk++) {
        CP_WAIT1();
        __syncthreads();

        if (chk + 2 < KCHUNKS)
            load_chunk(A16, B16, aRowBase, n0, tid, chk + 2,
                       sbase + ((chk + 2) % NSTG) * STG_B);
        CP_COMMIT();

        const uint32_t stg = sbase + (chk % NSTG) * STG_B;
        const uint32_t tA  = stg + 0 * TILE_B;
        const uint32_t tB  = stg + 1 * TILE_B;

        #pragma unroll
        for (int k16 = 0; k16 < 4; k16++) {
            const int kb = k16 * 32 + kQ;
            uint32_t Af[2][4];
            #pragma unroll
            for (int mt = 0; mt < 2; mt++)
                ldsm4(Af[mt], swaddr(tA, wr * 32 + mt * 16 + (q & 1) * 8 + lr, kb));
            #pragma unroll
            for (int g = 0; g < 4; g++) {
                uint32_t Bf[4];
                ldsm4(Bf, swaddr(tB, wc * 64 + g * 16 + (q & 1) * 8 + lr, kb));
                #pragma unroll
                for (int s = 0; s < 2; s++) {
                    const int nt = g * 2 + s;
                    #pragma unroll
                    for (int mt = 0; mt < 2; mt++)
                        mma16816(acc[mt][nt], Af[mt], Bf[s], Bf[s + 2]);
                }
            }
        }
    }

    // epilogue
    #pragma unroll
    for (int mt = 0; mt < 2; mt++) {
        const int row = m0 + wr * 32 + mt * 16 + (lane >> 2);
        #pragma unroll
        for (int nt = 0; nt < 8; nt++) {
            const int col = n0 + wc * 64 + nt * 8 + 2 * (lane & 3);
            const float bb0 = bias[col], bb1 = bias[col + 1];
            float v0 = acc[mt][nt][0] + bb0;
            float v1 = acc[mt][nt][1] + bb1;
            float v2 = acc[mt][nt][2] + bb0;
            float v3 = acc[mt][nt][3] + bb1;
            if (act) {
                v0 = (v0 > 0.f) ? (v0 + 1.f) : expf(v0);
                v1 = (v1 > 0.f) ? (v1 + 1.f) : expf(v1);
                v2 = (v2 > 0.f) ? (v2 + 1.f) : expf(v2);
                v3 = (v3 > 0.f) ? (v3 + 1.f) : expf(v3);
            }
            if (outhalf) {
                __half* Ch = (__half*)Cv;
                *(uint32_t*)(Ch + (size_t)row * DM + col)       = pack2(v0, v1);
                *(uint32_t*)(Ch + (size_t)(row + 8) * DM + col) = pack2(v2, v3);
            } else {
                float* C = (float*)Cv;
                *(float2*)(C + (size_t)row * DM + col)       = make_float2(v0, v1);
                *(float2*)(C + (size_t)(row + 8) * DM + col) = make_float2(v2, v3);
            }
        }
    }
}

// ---------------------------------------------------------------------------
// Scan kernel A: per-chunk S[c][a] = sum_j V[j][c] K[j][a] and Z[a] (tensor cores)
// 128 threads, 4 warps (warp tile 32c x 32a).
// ---------------------------------------------------------------------------
__global__ __launch_bounds__(128, 4)
void attn_chunk_sums(const __half* __restrict__ K16,
                     const __half* __restrict__ V16,
                     float* __restrict__ S,
                     float* __restrict__ Z)
{
    __shared__ __align__(128) __half sK[64 * 64];
    __shared__ __align__(128) __half sV[64 * 64];

    const int ch = blockIdx.x, bh = blockIdx.y;
    const int b = bh >> 4, h = bh & 15;
    const size_t base = ((size_t)(b * L_ + ch * CH)) * DM + h * HD;
    const int tid = threadIdx.x;
    const uint32_t uK = smem_u32(sK), uV = smem_u32(sV);

    for (int f = tid; f < 512; f += 128) {
        const int r = f >> 3, c = f & 7;
        *(uint4*)((char*)sK + swaddr(0, r, c * 16)) =
            *(const uint4*)(K16 + base + (size_t)r * DM + c * 8);
        *(uint4*)((char*)sV + swaddr(0, r, c * 16)) =
            *(const uint4*)(V16 + base + (size_t)r * DM + c * 8);
    }
    __syncthreads();

    const int wid = tid >> 5, lane = tid & 31;
    const int q = lane >> 3, lr = lane & 7;
    const int c0 = (wid >> 1) * 32, a0 = (wid & 1) * 32;

    float sacc[2][4][4];
    #pragma unroll
    for (int mt = 0; mt < 2; mt++)
        #pragma unroll
        for (int nt = 0; nt < 4; nt++)
            #pragma unroll
            for (int e = 0; e < 4; e++) sacc[mt][nt][e] = 0.f;

    #pragma unroll
    for (int jk = 0; jk < 4; jk++) {
        uint32_t Af[2][4];
        #pragma unroll
        for (int mt = 0; mt < 2; mt++)
            ldsm4t(Af[mt], taddr(uV, jk * 16, c0 + mt * 16, q, lr));
        #pragma unroll
        for (int nb = 0; nb < 2; nb++) {
            uint32_t Bf[4];
            ldsm4t(Bf, taddr(uK, jk * 16, a0 + nb * 16, q, lr));
            #pragma unroll
            for (int s = 0; s < 2; s++)
                #pragma unroll
                for (int mt = 0; mt < 2; mt++)
                    mma16816(sacc[mt][nb * 2 + s], Af[mt], Bf[s], Bf[s + 2]);
        }
    }

    float* sout = S + ((size_t)bh * NCH + ch) * (HD * HD);
    #pragma unroll
    for (int mt = 0; mt < 2; mt++)
        #pragma unroll
        for (int nt = 0; nt < 4; nt++) {
            const int c = c0 + mt * 16 + (lane >> 2);
            const int a = a0 + nt * 8 + 2 * (lane & 3);
            *(float2*)(sout + (size_t)c * HD + a) =
                make_float2(sacc[mt][nt][0], sacc[mt][nt][1]);
            *(float2*)(sout + (size_t)(c + 8) * HD + a) =
                make_float2(sacc[mt][nt][2], sacc[mt][nt][3]);
        }

    if (tid < 64) {
        float s0 = 0.f, s1 = 0.f;
        #pragma unroll 8
        for (int j = 0; j < 64; j += 2) {
            s0 += __half2float(*(const __half*)((const char*)sK + swaddr(0, j, tid * 2)));
            s1 += __half2float(*(const __half*)((const char*)sK + swaddr(0, j + 1, tid * 2)));
        }
        Z[((size_t)bh * NCH + ch) * HD + tid] = s0 + s1;
    }
}

// ---------------------------------------------------------------------------
// Scan kernel B: exclusive prefix over chunks (unchanged).
// ---------------------------------------------------------------------------
__global__ __launch_bounds__(512, 1)
void attn_prefix(float* __restrict__ S, float* __restrict__ Z)
{
    const int bh = blockIdx.x;
    const int tid = threadIdx.x;
    const size_t sb = (size_t)bh * NCH * (HD * HD);

    float run[8];
    #pragma unroll
    for (int u = 0; u < 8; u++) run[u] = 0.f;

    for (int ch = 0; ch < NCH; ch++) {
        #pragma unroll
        for (int u = 0; u < 8; u++) {
            const size_t idx = sb + (size_t)ch * (HD * HD) + tid + u * 512;
            float t = S[idx];
            S[idx] = run[u];
            run[u] += t;
        }
    }

    if (tid < 64) {
        const size_t zb = (size_t)bh * NCH * HD;
        float rz = 0.f;
        for (int ch = 0; ch < NCH; ch++) {
            float t = Z[zb + (size_t)ch * HD + tid];
            Z[zb + (size_t)ch * HD + tid] = rz;
            rz += t;
        }
    }
}

// ---------------------------------------------------------------------------
// Scan kernel C: per-chunk outputs, tensorized. 256 threads, 8 warps.
//   gacc = Q Vt (masked j<=i) -> fp16 A frags -> num = G K + Q Sprev
//   out[i][a] = num / (q[i][a] * Zcum[i][a] + eps)  -> fp16 (A16 slab 0)
// ---------------------------------------------------------------------------
__global__ __launch_bounds__(256, 2)
void attn_chunk_out(const __half* __restrict__ Q16,
                    const __half* __restrict__ K16,
                    const __half* __restrict__ V16,
                    const float* __restrict__ Sp,
                    const float* __restrict__ Zp,
                    __half* __restrict__ O16)
{
    extern __shared__ char cosm[];
    const uint32_t ub = smem_u32(cosm);

    const int ch = blockIdx.x, bh = blockIdx.y;
    const int b = bh >> 4, h = bh & 15;
    const size_t base = ((size_t)(b * L_ + ch * CH)) * DM + h * HD;
    const int tid = threadIdx.x;

    // loads: Q, V, K fp16 tiles (swizzled)
    for (int f = tid; f < 512; f += 256) {
        const int r = f >> 3, c = f & 7;
        const uint32_t sw = swaddr(0, r, c * 16);
        *(uint4*)(cosm + CO_Q + sw) = *(const uint4*)(Q16 + base + (size_t)r * DM + c * 8);
        *(uint4*)(cosm + CO_V + sw) = *(const uint4*)(V16 + base + (size_t)r * DM + c * 8);
        *(uint4*)(cosm + CO_K + sw) = *(const uint4*)(K16 + base + (size_t)r * DM + c * 8);
    }
    // Sp fp32 -> fp16 swizzled
    {
        const float* sp = Sp + ((size_t)bh * NCH + ch) * (HD * HD);
        #pragma unroll
        for (int it = 0; it < 4; it++) {
            const int e = (tid + it * 256) * 4;
            const int c = e >> 6, a = e & 63;
            float4 v = *(const float4*)(sp + (size_t)c * HD + a);
            uint2 u;
            u.x = pack2(v.x, v.y);
            u.y = pack2(v.z, v.w);
            *(uint2*)(cosm + CO_SP + swaddr(0, c, a * 2)) = u;
        }
    }
    __syncthreads();

    const int wid = tid >> 5, lane = tid & 31;
    const int q = lane >> 3, lr = lane & 7;
    const int wr = wid & 3, wc = wid >> 2;
    const int i0 = wr * 16, j0 = wc * 32;
    const bool active = (j0 <= i0 + 15);

    const uint32_t uQ = ub + CO_Q, uV = ub + CO_V, uK = ub + CO_K, uSp = ub + CO_SP;

    float numacc[8][4];
    #pragma unroll
    for (int nt = 0; nt < 8; nt++)
        #pragma unroll
        for (int e = 0; e < 4; e++) numacc[nt][e] = 0.f;

    if (active) {
        float gacc[4][4];
        #pragma unroll
        for (int nt = 0; nt < 4; nt++)
            #pragma unroll
            for (int e = 0; e < 4; e++) gacc[nt][e] = 0.f;

        #pragma unroll
        for (int kc = 0; kc < 4; kc++) {
            const int kb = kc * 32 + (q >> 1) * 16;
            uint32_t Aq[4];
            ldsm4(Aq, naddr(uQ, i0, kc * 32, q, lr));
            // Phase A: G += Q . Vt  (B = V[j][c] natural)
            #pragma unroll
            for (int g = 0; g < 2; g++) {
                uint32_t Bv[4];
                ldsm4(Bv, swaddr(uV, j0 + g * 16 + (q & 1) * 8 + lr, kb));
                mma16816(gacc[g * 2 + 0], Aq, Bv[0], Bv[2]);
                mma16816(gacc[g * 2 + 1], Aq, Bv[1], Bv[3]);
            }
            // Phase C (once per i-tile, wc==0): num += Q . Sprev
            if (wc == 0) {
                #pragma unroll
                for (int nb = 0; nb < 4; nb++) {
                    uint32_t Bs[4];
                    ldsm4t(Bs, taddr(uSp, kc * 16, nb * 16, q, lr));
                    mma16816(numacc[nb * 2 + 0], Aq, Bs[0], Bs[2]);
                    mma16816(numacc[nb * 2 + 1], Aq, Bs[1], Bs[3]);
                }
            }
        }

        // causal mask (keep j <= i)
        #pragma unroll
        for (int nt = 0; nt < 4; nt++) {
            const int jb = j0 + nt * 8 + 2 * (lane & 3);
            const int ib = i0 + (lane >> 2);
            if (jb     > ib)     gacc[nt][0] = 0.f;
            if (jb + 1 > ib)     gacc[nt][1] = 0.f;
            if (jb     > ib + 8) gacc[nt][2] = 0.f;
            if (jb + 1 > ib + 8) gacc[nt][3] = 0.f;
        }
        // pack G -> A fragments (2 k16 steps over j)
        uint32_t aG[2][4];
        #pragma unroll
        for (int t = 0; t < 2; t++) {
            aG[t][0] = pack2(gacc[2 * t][0],     gacc[2 * t][1]);
            aG[t][1] = pack2(gacc[2 * t][2],     gacc[2 * t][3]);
            aG[t][2] = pack2(gacc[2 * t + 1][0], gacc[2 * t + 1][1]);
            aG[t][3] = pack2(gacc[2 * t + 1][2], gacc[2 * t + 1][3]);
        }
        // Phase B: num += G . K   (B[n=a][k=j] trans from K[j][a])
        #pragma unroll
        for (int t = 0; t < 2; t++)
            #pragma unroll
            for (int nb = 0; nb < 4; nb++) {
                uint32_t Bk[4];
                ldsm4t(Bk, taddr(uK, j0 + t * 16, nb * 16, q, lr));
                mma16816(numacc[nb * 2 + 0], aG[t], Bk[0], Bk[2]);
                mma16816(numacc[nb * 2 + 1], aG[t], Bk[1], Bk[3]);
            }
    }

    // cross-warp reduction (j-upper-half partials from wc==1, wr>=2)
    if (wc == 1 && wr >= 2) {
        float* red = (float*)(cosm + CO_RED) + (size_t)(wr - 2) * 16 * 68;
        #pragma unroll
        for (int nt = 0; nt < 8; nt++) {
            const int r = lane >> 2, a = nt * 8 + 2 * (lane & 3);
            *(float2*)(red + r * 68 + a)       = make_float2(numacc[nt][0], numacc[nt][1]);
            *(float2*)(red + (r + 8) * 68 + a) = make_float2(numacc[nt][2], numacc[nt][3]);
        }
    }
    __syncthreads();

    if (wc == 0) {
        if (wr >= 2) {
            const float* red = (const float*)(cosm + CO_RED) + (size_t)(wr - 2) * 16 * 68;
            #pragma unroll
            for (int nt = 0; nt < 8; nt++) {
                const int r = lane >> 2, a = nt * 8 + 2 * (lane & 3);
                float2 p0 = *(const float2*)(red + r * 68 + a);
                float2 p1 = *(const float2*)(red + (r + 8) * 68 + a);
                numacc[nt][0] += p0.x; numacc[nt][1] += p0.y;
                numacc[nt][2] += p1.x; numacc[nt][3] += p1.y;
            }
        }
        float* nm = (float*)(cosm + CO_NUM);
        #pragma unroll
        for (int nt = 0; nt < 8; nt++) {
            const int r = wr * 16 + (lane >> 2), a = nt * 8 + 2 * (lane & 3);
            *(float2*)(nm + r * 72 + a)       = make_float2(numacc[nt][0], numacc[nt][1]);
            *(float2*)(nm + (r + 8) * 72 + a) = make_float2(numacc[nt][2], numacc[nt][3]);
        }
    }
    __syncthreads();

    // Phase D: Zcum[i][a] = Zp[a] + cumsum_{j<=i} K[j][a]  (segmented scan)
    {
        const int az = tid & 63, seg = tid >> 6;
        float s16 = 0.f;
        #pragma unroll
        for (int i2 = 0; i2 < 16; i2++)
            s16 += __half2float(*(const __half*)(cosm + CO_K + swaddr(0, seg * 16 + i2, az * 2)));
        float* part = (float*)(cosm + CO_PART);
        part[seg * 64 + az] = s16;
        __syncthreads();
        float run = Zp[((size_t)bh * NCH + ch) * HD + az];
        #pragma unroll
        for (int s2 = 0; s2 < 3; s2++)
            if (s2 < seg) run += part[s2 * 64 + az];
        float* zw = (float*)(cosm + CO_ZW);
        #pragma unroll
        for (int i2 = 0; i2 < 16; i2++) {
            run += __half2float(*(const __half*)(cosm + CO_K + swaddr(0, seg * 16 + i2, az * 2)));
            zw[(seg * 16 + i2) * 64 + az] = run;
        }
    }
    __syncthreads();

    // Phase E
    {
        const int tx = tid & 15, ty = tid >> 4;
        const float* nm = (const float*)(cosm + CO_NUM);
        const float* zw = (const float*)(cosm + CO_ZW);
        #pragma unroll
        for (int ii = 0; ii < 4; ii++) {
            const int i = ty * 4 + ii;
            float4 n4 = *(const float4*)(nm + i * 72 + tx * 4);
            float4 z4 = *(const float4*)(zw + i * 64 + tx * 4);
            unsigned short o[4];
            #pragma unroll
            for (int aa = 0; aa < 4; aa++) {
                const int a = tx * 4 + aa;
                const float qv = __half2float(
                    *(const __half*)(cosm + CO_Q + swaddr(0, i, a * 2)));
                o[aa] = __half_as_ushort(
                    __float2half_rn((&n4.x)[aa] / (qv * (&z4.x)[aa] + EPSC)));
            }
            uint2 u;
            u.x = (uint32_t)o[0] | ((uint32_t)o[1] << 16);
            u.y = (uint32_t)o[2] | ((uint32_t)o[3] << 16);
            *(uint2*)(O16 + base + (size_t)i * DM + tx * 4) = u;
        }
    }
}

// ---------------------------------------------------------------------------
// kernel_launch
// ---------------------------------------------------------------------------
extern "C" void kernel_launch(void* const* d_in, const int* in_sizes, int n_in,
                              void* d_out, int out_size)
{
    const float* queries = (const float*)d_in[0];
    const float* keys    = (const float*)d_in[1];
    const float* values  = (const float*)d_in[2];
    const float* Wq = (const float*)d_in[3];
    const float* bq = (const float*)d_in[4];
    const float* Wk = (const float*)d_in[5];
    const float* bk = (const float*)d_in[6];
    const float* Wv = (const float*)d_in[7];
    const float* bv = (const float*)d_in[8];
    const float* Wo = (const float*)d_in[9];
    const float* bo = (const float*)d_in[10];
    float* out = (float*)d_out;

    float *pS, *pZ;
    __half *pA16, *pW16, *pQ16, *pK16, *pV16;
    cudaGetSymbolAddress((void**)&pS, g_S);
    cudaGetSymbolAddress((void**)&pZ, g_Z);
    cudaGetSymbolAddress((void**)&pA16, g_A16);
    cudaGetSymbolAddress((void**)&pW16, g_W16);
    cudaGetSymbolAddress((void**)&pQ16, g_Q16);
    cudaGetSymbolAddress((void**)&pK16, g_K16);
    cudaGetSymbolAddress((void**)&pV16, g_V16);

    cudaFuncSetAttribute(gemm_tc_kernel,
                         cudaFuncAttributeMaxDynamicSharedMemorySize, SMEM_GEMM);
    cudaFuncSetAttribute(attn_chunk_out,
                         cudaFuncAttributeMaxDynamicSharedMemorySize, CO_SMEM);

    // 1) weight converts (4 slabs)
    conv_w_all<<<dim3(DM / 32, DM / 32, 4), 256>>>(Wq, Wk, Wv, Wo, pW16);
    // 2) input converts (3 slabs)
    conv_a_all<<<dim3(M_ * DM / 1024, 3), 256>>>(queries, keys, values, pA16);
    // 3) projections -> fp16 Q,K,V (act on q,k)
    gemm_tc_kernel<<<dim3(DM / 128, M_ / 128, 3), 256, SMEM_GEMM>>>(
        pA16, pW16, bq, bk, bv, pQ16, pK16, pV16, 0b011, 1);
    // 4) chunked causal linear attention (tensorized) -> fp16 A16 slab 0
    {
        dim3 chunk_grid(NCH, B_ * H_);
        attn_chunk_sums<<<chunk_grid, 128>>>(pK16, pV16, pS, pZ);
        attn_prefix<<<B_ * H_, 512>>>(pS, pZ);
        attn_chunk_out<<<chunk_grid, 256, CO_SMEM>>>(pQ16, pK16, pV16, pS, pZ, pA16);
    }
    // 5) output projection (W slab 3), fp32 out
    gemm_tc_kernel<<<dim3(DM / 128, M_ / 128, 1), 256, SMEM_GEMM>>>(
        pA16, pW16 + (size_t)3 * DM * DM, bo, bo, bo, out, out, out, 0, 0);
}